// round 11
// baseline (speedup 1.0000x reference)
#include <cuda_runtime.h>
#include <cuda_fp16.h>
#include <math.h>
#include <stdint.h>

// ---------------- problem constants ----------------
#define LEN   16384
#define LOUT  4096
#define PB    127          // primary patches per block
#define PQ    508          // exclusive padded positions per block
#define NBLK  33

// ---------------- smem layout (bytes) ----------------
#define ROWB     144        // fp16 row stride (72 halves): ldmatrix conflict-free
#define OFF_A    0          // A fp16 [128][72]  (feats, then h)
#define OFF_W1   18432      // W1 fp16 [64][72] = 9216B
#define OFF_W2   27648      // W2 fp16 [64][72] = 9216B
#define OFF_B1S  36864      // float[64]
#define OFF_B2S  37120      // float[64]
#define SMEM_BYTES 37376
#define OFF_OS   0          // float[128][68] = 34816B, aliases A+W1 (+W2 head,
#define OS_ROW   68         //   written only after GEMM2 completes)

// pre-packed fp16 weight image: W1 = words [0,2304), W2 = words [2304,4608)
__device__ uint4 g_wpack4[1152];

__device__ __forceinline__ uint32_t smem_u32(const void* p) {
    uint32_t a;
    asm("{ .reg .u64 t; cvta.to.shared.u64 t, %1; cvt.u32.u64 %0, t; }"
        : "=r"(a) : "l"(p));
    return a;
}

__device__ __forceinline__ void ldsm4(uint32_t r[4], uint32_t addr) {
    asm volatile("ldmatrix.sync.aligned.m8n8.x4.shared.b16 {%0,%1,%2,%3}, [%4];"
                 : "=r"(r[0]), "=r"(r[1]), "=r"(r[2]), "=r"(r[3]) : "r"(addr));
}

__device__ __forceinline__ void stsm4(uint32_t addr, uint32_t r0, uint32_t r1,
                                      uint32_t r2, uint32_t r3) {
    asm volatile("stmatrix.sync.aligned.m8n8.x4.shared.b16 [%0], {%1,%2,%3,%4};"
                 :: "r"(addr), "r"(r0), "r"(r1), "r"(r2), "r"(r3) : "memory");
}

__device__ __forceinline__ void mma16816(float c[4], const uint32_t a[4],
                                         const uint32_t* b) {
    asm volatile(
        "mma.sync.aligned.m16n8k16.row.col.f32.f16.f16.f32 "
        "{%0,%1,%2,%3}, {%4,%5,%6,%7}, {%8,%9}, {%0,%1,%2,%3};"
        : "+f"(c[0]), "+f"(c[1]), "+f"(c[2]), "+f"(c[3])
        : "r"(a[0]), "r"(a[1]), "r"(a[2]), "r"(a[3]), "r"(b[0]), "r"(b[1]));
}

__device__ __forceinline__ uint32_t pack_h2(float g0, float g1) {
    uint32_t p;
    asm("cvt.rn.f16x2.f32 %0, %1, %2;" : "=r"(p) : "f"(g1), "f"(g0));
    return p;
}

// ---- prep kernel: pack W1/W2 fp32 -> fp16 smem-image in global ----
__global__ void weight_pack_kernel(const float* __restrict__ W1,
                                   const float* __restrict__ W2) {
    uint32_t* w = (uint32_t*)g_wpack4;
    int i = blockIdx.x * 256 + threadIdx.x;      // 0..2047
    if (i >= 2048) return;
    int nr = i >> 5, k2 = (i & 31) << 1;
    int word = nr * 36 + (k2 >> 1);
    w[word]        = pack_h2(W1[nr * 64 + k2], W1[nr * 64 + k2 + 1]);
    w[2304 + word] = pack_h2(W2[nr * 64 + k2], W2[nr * 64 + k2 + 1]);
}

// single-term fp16 GEMM, warp tile 32x32: C[8][4] += A @ W^T
__device__ __forceinline__ void warp_gemm64(uint32_t aB, uint32_t b0, uint32_t b1,
                                            float C[8][4]) {
    #pragma unroll
    for (int ks = 0; ks < 4; ks++) {
        uint32_t a[2][4], b[4][2], r[4];
        ldsm4(a[0], aB + ks * 32);
        ldsm4(a[1], aB + 16 * ROWB + ks * 32);
        ldsm4(r, b0 + ks * 32);
        b[0][0]=r[0]; b[0][1]=r[1]; b[1][0]=r[2]; b[1][1]=r[3];
        ldsm4(r, b1 + ks * 32);
        b[2][0]=r[0]; b[2][1]=r[1]; b[3][0]=r[2]; b[3][1]=r[3];
        #pragma unroll
        for (int i = 0; i < 2; i++)
            #pragma unroll
            for (int j = 0; j < 4; j++)
                mma16816(C[i * 4 + j], a[i], b[j]);
    }
}

__global__ __launch_bounds__(256, 4)
void fused_hmma_kernel(const float* __restrict__ x,
                       const float* __restrict__ b1,
                       const float* __restrict__ b2,
                       float* __restrict__ out)
{
    extern __shared__ char smc[];
    const uint32_t sbase = smem_u32(smc);
    float* b1s = (float*)(smc + OFF_B1S);
    float* b2s = (float*)(smc + OFF_B2S);
    float* o_s = (float*)(smc + OFF_OS);

    const int tid  = threadIdx.x;
    const int lane = tid & 31;
    const int wid  = tid >> 5;
    const int blk  = blockIdx.x;
    const int n    = blockIdx.y;
    const int wm = wid >> 1, wn = wid & 1;
    const int m0 = 32 * wm,  n0 = 32 * wn;
    const int gid = lane >> 2, tig = lane & 3;

    // lane-resolved ldmatrix offsets
    const uint32_t aOff  = (uint32_t)(m0 + (lane & 15)) * ROWB + (lane >> 4) * 16;
    const uint32_t bOff0 = (uint32_t)(n0 + ((lane >> 4) & 1) * 8 + (lane & 7)) * ROWB
                         + ((lane >> 3) & 1) * 16;
    const uint32_t bOff1 = bOff0 + 16 * ROWB;
    // stmatrix lane address template: matrix m = lane>>3 -> (half = m&1, cj = m>>1)
    const uint32_t stm = sbase + OFF_A
        + (uint32_t)(m0 + 8 * ((lane >> 3) & 1) + (lane & 7)) * ROWB
        + (uint32_t)(n0 + 8 * (lane >> 4)) * 2;

    // ---- Phase 1: weights via cp.async (overlaps x loads); x -> fp16 A ----
    {
        #pragma unroll
        for (int i = 0; i < 5; i++) {
            int idx = tid + 256 * i;
            if (idx < 1152) {
                uint32_t dst = sbase + OFF_W1 + (uint32_t)idx * 16;
                asm volatile("cp.async.cg.shared.global [%0], [%1], 16;"
                             :: "r"(dst), "l"(g_wpack4 + idx));
            }
        }
        asm volatile("cp.async.commit_group;" ::: "memory");

        const float* xn = x + (size_t)n * 8 * LEN;
        const int t = tid & 127;
        const int chalf = tid >> 7;               // 0/1 -> channels 0-3 / 4-7
        const int idx0 = PQ * blk - 6 + 4 * t;    // x index of tap k=0
        const bool interior = (idx0 >= 0) && (idx0 + 7 < LEN);
        #pragma unroll
        for (int cc = 0; cc < 4; cc++) {
            int c = chalf * 4 + cc;
            const float* xp = xn + c * LEN;
            float v[8];
            if (interior) {
                #pragma unroll
                for (int jj = 0; jj < 4; jj++) {
                    float2 u = *(const float2*)(xp + idx0 + 2 * jj);
                    v[2 * jj] = u.x; v[2 * jj + 1] = u.y;
                }
            } else {
                #pragma unroll
                for (int j = 0; j < 8; j++) {
                    int ix = idx0 + j;
                    v[j] = (ix >= 0 && ix < LEN) ? xp[ix] : 0.0f;
                }
            }
            uint4 w;
            w.x = pack_h2(v[0], v[1]); w.y = pack_h2(v[2], v[3]);
            w.z = pack_h2(v[4], v[5]); w.w = pack_h2(v[6], v[7]);
            *(uint4*)(smc + OFF_A + t * ROWB + c * 16) = w;
        }
        if (tid < 64) { b1s[tid] = b1[tid]; b2s[tid] = b2[tid]; }
        asm volatile("cp.async.wait_group 0;" ::: "memory");
    }
    __syncthreads();

    // ---- GEMM1: feats @ W1^T ----
    float C1[8][4];
    #pragma unroll
    for (int i = 0; i < 8; i++)
        #pragma unroll
        for (int j = 0; j < 4; j++) C1[i][j] = 0.0f;
    warp_gemm64(sbase + OFF_A + aOff,
                sbase + OFF_W1 + bOff0, sbase + OFF_W1 + bOff1, C1);
    // pair barrier: only the 2 warps of this M-band read/write these A rows
    asm volatile("bar.sync %0, 64;" :: "r"(wm + 1) : "memory");

    // ---- Epilogue 1: +b1, exact GELU -> fp16 A region via stmatrix ----
    {
        uint32_t p01[2][4], p23[2][4];
        #pragma unroll
        for (int i = 0; i < 2; i++) {
            #pragma unroll
            for (int j = 0; j < 4; j++) {
                float* c = C1[i * 4 + j];
                int col = n0 + 8 * j + 2 * tig;
                float bb0 = b1s[col], bb1 = b1s[col + 1];
                float v00 = c[0] + bb0, v01 = c[1] + bb1;
                float v10 = c[2] + bb0, v11 = c[3] + bb1;
                float g00 = 0.5f * v00 * (1.0f + erff(v00 * 0.70710678118654752f));
                float g01 = 0.5f * v01 * (1.0f + erff(v01 * 0.70710678118654752f));
                float g10 = 0.5f * v10 * (1.0f + erff(v10 * 0.70710678118654752f));
                float g11 = 0.5f * v11 * (1.0f + erff(v11 * 0.70710678118654752f));
                p01[i][j] = pack_h2(g00, g01);
                p23[i][j] = pack_h2(g10, g11);
            }
        }
        #pragma unroll
        for (int i = 0; i < 2; i++)
            #pragma unroll
            for (int j0 = 0; j0 < 4; j0 += 2)
                stsm4(stm + i * 16 * ROWB + j0 * 16,
                      p01[i][j0], p23[i][j0], p01[i][j0 + 1], p23[i][j0 + 1]);
    }
    asm volatile("bar.sync %0, 64;" :: "r"(wm + 1) : "memory");

    // ---- GEMM2: h @ W2^T ----
    float C2[8][4];
    #pragma unroll
    for (int i = 0; i < 8; i++)
        #pragma unroll
        for (int j = 0; j < 4; j++) C2[i][j] = 0.0f;
    warp_gemm64(sbase + OFF_A + aOff,
                sbase + OFF_W2 + bOff0, sbase + OFF_W2 + bOff1, C2);
    __syncthreads();   // o_s aliases A/W1/W2-head across all bands

    // ---- Epilogue 2: +b2 -> o_s[t][o] fp32 ----
    #pragma unroll
    for (int i = 0; i < 2; i++) {
        #pragma unroll
        for (int j = 0; j < 4; j++) {
            float* c = C2[i * 4 + j];
            int col = n0 + 8 * j + 2 * tig;
            float bb0 = b2s[col], bb1 = b2s[col + 1];
            int row0 = m0 + 16 * i + gid;
            *(float2*)(o_s + row0 * OS_ROW + col) =
                make_float2(c[0] + bb0, c[1] + bb1);
            *(float2*)(o_s + (row0 + 8) * OS_ROW + col) =
                make_float2(c[2] + bb0, c[3] + bb1);
        }
    }
    __syncthreads();

    // ---- Phase 5: vectorized overlap-add (group = 4 outputs of one l1) ----
    const int lbase = PB * blk - 1;
    float* outn = out + (size_t)n * 8 * LEN;
    if (blk >= 1 && blk <= 31) {
        // whole CTA interior: uniform fast path, no per-element bounds checks
        #pragma unroll
        for (int it = 0; it < 4; it++) {
            int g = tid + it * 256;
            int gi = g & 127;
            if (gi == 0) continue;
            int c = g >> 7;
            float4 a1 = *(float4*)(o_s + gi * OS_ROW + c * 8);
            float4 a0 = *(float4*)(o_s + (gi - 1) * OS_ROW + c * 8 + 4);
            float* op = outn + c * LEN + 4 * (lbase + gi) - 2;
            *(float2*)(op)     = make_float2(0.5f * (a1.x + a0.x), 0.5f * (a1.y + a0.y));
            *(float2*)(op + 2) = make_float2(0.5f * (a1.z + a0.z), 0.5f * (a1.w + a0.w));
        }
    } else {
        #pragma unroll
        for (int it = 0; it < 4; it++) {
            int g = tid + it * 256;
            int gi = g & 127;
            if (gi == 0) continue;
            int c = g >> 7;
            int l1 = lbase + gi;
            float* orow = outn + c * LEN;
            if (l1 >= 1 && l1 <= LOUT - 1) {
                float4 a1 = *(float4*)(o_s + gi * OS_ROW + c * 8);
                float4 a0 = *(float4*)(o_s + (gi - 1) * OS_ROW + c * 8 + 4);
                int ob = 4 * l1 - 2;
                *(float2*)(orow + ob) =
                    make_float2(0.5f * (a1.x + a0.x), 0.5f * (a1.y + a0.y));
                *(float2*)(orow + ob + 2) =
                    make_float2(0.5f * (a1.z + a0.z), 0.5f * (a1.w + a0.w));
            } else {
                #pragma unroll
                for (int k1 = 0; k1 < 4; k1++) {
                    int q = 4 * l1 + k1;
                    if (q < 2 || q > LEN + 1) continue;
                    float v = 0.0f; int cnt = 0;
                    if (l1 < LOUT) { v += o_s[gi * OS_ROW + c * 8 + k1];           cnt++; }
                    if (l1 >= 1)   { v += o_s[(gi - 1) * OS_ROW + c * 8 + k1 + 4]; cnt++; }
                    orow[q - 2] = (cnt == 2) ? v * 0.5f : v;
                }
            }
        }
    }
}

extern "C" void kernel_launch(void* const* d_in, const int* in_sizes, int n_in,
                              void* d_out, int out_size)
{
    const float* x  = (const float*)d_in[0];
    const float* W1 = (const float*)d_in[1];
    const float* b1 = (const float*)d_in[2];
    const float* W2 = (const float*)d_in[3];
    const float* b2 = (const float*)d_in[4];
    float* out = (float*)d_out;

    weight_pack_kernel<<<8, 256>>>(W1, W2);

    cudaFuncSetAttribute(fused_hmma_kernel,
                         cudaFuncAttributeMaxDynamicSharedMemorySize, SMEM_BYTES);
    dim3 grid(NBLK, 64);
    fused_hmma_kernel<<<grid, 256, SMEM_BYTES>>>(x, b1, b2, out);
}

// round 12
// speedup vs baseline: 1.1380x; 1.1380x over previous
#include <cuda_runtime.h>
#include <cuda_fp16.h>
#include <math.h>
#include <stdint.h>

// ---------------- problem constants ----------------
#define LEN   16384
#define LOUT  4096
#define PB    127          // primary patches per block
#define PQ    508          // exclusive padded positions per block
#define NBLK  33

// ---------------- smem layout (bytes) ----------------
#define ROWB     144        // fp16 row stride (72 halves): ldmatrix conflict-free
#define OFF_A    0          // A fp16 [128][72]  (feats, then h)
#define OFF_W1   18432      // W1 fp16 [64][72] = 9216B
#define OFF_W2   27648      // W2 fp16 [64][72] = 9216B
#define OFF_B1S  36864      // float[64]
#define OFF_B2S  37120      // float[64]
#define SMEM_BYTES 37376
#define OFF_OS   0          // float[128][68] = 34816B, aliases A+W1 (+W2 head,
#define OS_ROW   68         //   written only after GEMM2 completes)

// pre-packed fp16 weight image: W1 = words [0,2304), W2 = words [2304,4608)
__device__ uint4 g_wpack4[1152];

__device__ __forceinline__ uint32_t smem_u32(const void* p) {
    uint32_t a;
    asm("{ .reg .u64 t; cvta.to.shared.u64 t, %1; cvt.u32.u64 %0, t; }"
        : "=r"(a) : "l"(p));
    return a;
}

__device__ __forceinline__ void ldsm4(uint32_t r[4], uint32_t addr) {
    asm volatile("ldmatrix.sync.aligned.m8n8.x4.shared.b16 {%0,%1,%2,%3}, [%4];"
                 : "=r"(r[0]), "=r"(r[1]), "=r"(r[2]), "=r"(r[3]) : "r"(addr));
}

__device__ __forceinline__ void mma16816(float c[4], const uint32_t a[4],
                                         const uint32_t* b) {
    asm volatile(
        "mma.sync.aligned.m16n8k16.row.col.f32.f16.f16.f32 "
        "{%0,%1,%2,%3}, {%4,%5,%6,%7}, {%8,%9}, {%0,%1,%2,%3};"
        : "+f"(c[0]), "+f"(c[1]), "+f"(c[2]), "+f"(c[3])
        : "r"(a[0]), "r"(a[1]), "r"(a[2]), "r"(a[3]), "r"(b[0]), "r"(b[1]));
}

__device__ __forceinline__ uint32_t pack_h2(float g0, float g1) {
    uint32_t p;
    asm("cvt.rn.f16x2.f32 %0, %1, %2;" : "=r"(p) : "f"(g1), "f"(g0));
    return p;
}

// fast GELU: tanh form with HW tanh.approx (MUFU). ~6 instructions.
__device__ __forceinline__ float gelu_fast(float v) {
    float u = v * fmaf(0.0356774081f, v * v, 0.7978845608f);
    float t;
    asm("tanh.approx.f32 %0, %1;" : "=f"(t) : "f"(u));
    return fmaf(0.5f * v, t, 0.5f * v);
}

// ---- prep kernel: pack W1/W2 fp32 -> fp16 smem-image in global ----
__global__ void weight_pack_kernel(const float* __restrict__ W1,
                                   const float* __restrict__ W2) {
    uint32_t* w = (uint32_t*)g_wpack4;
    int i = blockIdx.x * 256 + threadIdx.x;      // 0..2047
    if (i >= 2048) return;
    int nr = i >> 5, k2 = (i & 31) << 1;
    int word = nr * 36 + (k2 >> 1);
    w[word]        = pack_h2(W1[nr * 64 + k2], W1[nr * 64 + k2 + 1]);
    w[2304 + word] = pack_h2(W2[nr * 64 + k2], W2[nr * 64 + k2 + 1]);
}

// single-term fp16 GEMM, warp tile 32x32: C[8][4] += A @ W^T
__device__ __forceinline__ void warp_gemm64(uint32_t aB, uint32_t b0, uint32_t b1,
                                            float C[8][4]) {
    #pragma unroll
    for (int ks = 0; ks < 4; ks++) {
        uint32_t a[2][4], b[4][2], r[4];
        ldsm4(a[0], aB + ks * 32);
        ldsm4(a[1], aB + 16 * ROWB + ks * 32);
        ldsm4(r, b0 + ks * 32);
        b[0][0]=r[0]; b[0][1]=r[1]; b[1][0]=r[2]; b[1][1]=r[3];
        ldsm4(r, b1 + ks * 32);
        b[2][0]=r[0]; b[2][1]=r[1]; b[3][0]=r[2]; b[3][1]=r[3];
        #pragma unroll
        for (int i = 0; i < 2; i++)
            #pragma unroll
            for (int j = 0; j < 4; j++)
                mma16816(C[i * 4 + j], a[i], b[j]);
    }
}

__global__ __launch_bounds__(256, 4)
void fused_hmma_kernel(const float* __restrict__ x,
                       const float* __restrict__ b1,
                       const float* __restrict__ b2,
                       float* __restrict__ out)
{
    extern __shared__ char smc[];
    const uint32_t sbase = smem_u32(smc);
    float* b1s = (float*)(smc + OFF_B1S);
    float* b2s = (float*)(smc + OFF_B2S);
    float* o_s = (float*)(smc + OFF_OS);

    const int tid  = threadIdx.x;
    const int lane = tid & 31;
    const int wid  = tid >> 5;
    const int blk  = blockIdx.x;
    const int n    = blockIdx.y;
    const int wm = wid >> 1, wn = wid & 1;
    const int m0 = 32 * wm,  n0 = 32 * wn;
    const int gid = lane >> 2, tig = lane & 3;

    // lane-resolved ldmatrix offsets
    const uint32_t aOff  = (uint32_t)(m0 + (lane & 15)) * ROWB + (lane >> 4) * 16;
    const uint32_t bOff0 = (uint32_t)(n0 + ((lane >> 4) & 1) * 8 + (lane & 7)) * ROWB
                         + ((lane >> 3) & 1) * 16;
    const uint32_t bOff1 = bOff0 + 16 * ROWB;

    // ---- Phase 1: weights via cp.async (overlaps x loads); x -> fp16 A ----
    {
        #pragma unroll
        for (int i = 0; i < 5; i++) {
            int idx = tid + 256 * i;
            if (idx < 1152) {
                uint32_t dst = sbase + OFF_W1 + (uint32_t)idx * 16;
                asm volatile("cp.async.cg.shared.global [%0], [%1], 16;"
                             :: "r"(dst), "l"(g_wpack4 + idx));
            }
        }
        asm volatile("cp.async.commit_group;" ::: "memory");

        const float* xn = x + (size_t)n * 8 * LEN;
        const int t = tid & 127;
        const int chalf = tid >> 7;               // 0/1 -> channels 0-3 / 4-7
        const int idx0 = PQ * blk - 6 + 4 * t;    // x index of tap k=0
        const bool interior = (idx0 >= 0) && (idx0 + 7 < LEN);
        #pragma unroll
        for (int cc = 0; cc < 4; cc++) {
            int c = chalf * 4 + cc;
            const float* xp = xn + c * LEN;
            float v[8];
            if (interior) {
                #pragma unroll
                for (int jj = 0; jj < 4; jj++) {
                    float2 u = *(const float2*)(xp + idx0 + 2 * jj);
                    v[2 * jj] = u.x; v[2 * jj + 1] = u.y;
                }
            } else {
                #pragma unroll
                for (int j = 0; j < 8; j++) {
                    int ix = idx0 + j;
                    v[j] = (ix >= 0 && ix < LEN) ? xp[ix] : 0.0f;
                }
            }
            uint4 w;
            w.x = pack_h2(v[0], v[1]); w.y = pack_h2(v[2], v[3]);
            w.z = pack_h2(v[4], v[5]); w.w = pack_h2(v[6], v[7]);
            *(uint4*)(smc + OFF_A + t * ROWB + c * 16) = w;
        }
        if (tid < 64) { b1s[tid] = b1[tid]; b2s[tid] = b2[tid]; }
        asm volatile("cp.async.wait_group 0;" ::: "memory");
    }
    __syncthreads();

    // ---- GEMM1: feats @ W1^T ----
    float C1[8][4];
    #pragma unroll
    for (int i = 0; i < 8; i++)
        #pragma unroll
        for (int j = 0; j < 4; j++) C1[i][j] = 0.0f;
    warp_gemm64(sbase + OFF_A + aOff,
                sbase + OFF_W1 + bOff0, sbase + OFF_W1 + bOff1, C1);
    // pair barrier: only the 2 warps of this M-band read/write these A rows
    asm volatile("bar.sync %0, 64;" :: "r"(wm + 1) : "memory");

    // ---- Epilogue 1: +b1, fast GELU -> fp16 A region (own band) ----
    #pragma unroll
    for (int i = 0; i < 2; i++) {
        #pragma unroll
        for (int j = 0; j < 4; j++) {
            float* c = C1[i * 4 + j];
            int col = n0 + 8 * j + 2 * tig;
            float bb0 = b1s[col], bb1 = b1s[col + 1];
            int row0 = m0 + 16 * i + gid;
            float g00 = gelu_fast(c[0] + bb0);
            float g01 = gelu_fast(c[1] + bb1);
            float g10 = gelu_fast(c[2] + bb0);
            float g11 = gelu_fast(c[3] + bb1);
            *(uint32_t*)(smc + OFF_A + row0 * ROWB + col * 2) = pack_h2(g00, g01);
            *(uint32_t*)(smc + OFF_A + (row0 + 8) * ROWB + col * 2) = pack_h2(g10, g11);
        }
    }
    asm volatile("bar.sync %0, 64;" :: "r"(wm + 1) : "memory");

    // ---- GEMM2: h @ W2^T ----
    float C2[8][4];
    #pragma unroll
    for (int i = 0; i < 8; i++)
        #pragma unroll
        for (int j = 0; j < 4; j++) C2[i][j] = 0.0f;
    warp_gemm64(sbase + OFF_A + aOff,
                sbase + OFF_W2 + bOff0, sbase + OFF_W2 + bOff1, C2);
    __syncthreads();   // o_s aliases A/W1/W2-head across all bands

    // ---- Epilogue 2: +b2 -> o_s[t][o] fp32 ----
    #pragma unroll
    for (int i = 0; i < 2; i++) {
        #pragma unroll
        for (int j = 0; j < 4; j++) {
            float* c = C2[i * 4 + j];
            int col = n0 + 8 * j + 2 * tig;
            float bb0 = b2s[col], bb1 = b2s[col + 1];
            int row0 = m0 + 16 * i + gid;
            *(float2*)(o_s + row0 * OS_ROW + col) =
                make_float2(c[0] + bb0, c[1] + bb1);
            *(float2*)(o_s + (row0 + 8) * OS_ROW + col) =
                make_float2(c[2] + bb0, c[3] + bb1);
        }
    }
    __syncthreads();

    // ---- Phase 5: vectorized overlap-add (group = 4 outputs of one l1) ----
    const int lbase = PB * blk - 1;
    float* outn = out + (size_t)n * 8 * LEN;
    if (blk >= 1 && blk <= 31) {
        // whole CTA interior: uniform fast path, no per-element bounds checks
        #pragma unroll
        for (int it = 0; it < 4; it++) {
            int g = tid + it * 256;
            int gi = g & 127;
            if (gi == 0) continue;
            int c = g >> 7;
            float4 a1 = *(float4*)(o_s + gi * OS_ROW + c * 8);
            float4 a0 = *(float4*)(o_s + (gi - 1) * OS_ROW + c * 8 + 4);
            float* op = outn + c * LEN + 4 * (lbase + gi) - 2;
            *(float2*)(op)     = make_float2(0.5f * (a1.x + a0.x), 0.5f * (a1.y + a0.y));
            *(float2*)(op + 2) = make_float2(0.5f * (a1.z + a0.z), 0.5f * (a1.w + a0.w));
        }
    } else {
        #pragma unroll
        for (int it = 0; it < 4; it++) {
            int g = tid + it * 256;
            int gi = g & 127;
            if (gi == 0) continue;
            int c = g >> 7;
            int l1 = lbase + gi;
            float* orow = outn + c * LEN;
            if (l1 >= 1 && l1 <= LOUT - 1) {
                float4 a1 = *(float4*)(o_s + gi * OS_ROW + c * 8);
                float4 a0 = *(float4*)(o_s + (gi - 1) * OS_ROW + c * 8 + 4);
                int ob = 4 * l1 - 2;
                *(float2*)(orow + ob) =
                    make_float2(0.5f * (a1.x + a0.x), 0.5f * (a1.y + a0.y));
                *(float2*)(orow + ob + 2) =
                    make_float2(0.5f * (a1.z + a0.z), 0.5f * (a1.w + a0.w));
            } else {
                #pragma unroll
                for (int k1 = 0; k1 < 4; k1++) {
                    int q = 4 * l1 + k1;
                    if (q < 2 || q > LEN + 1) continue;
                    float v = 0.0f; int cnt = 0;
                    if (l1 < LOUT) { v += o_s[gi * OS_ROW + c * 8 + k1];           cnt++; }
                    if (l1 >= 1)   { v += o_s[(gi - 1) * OS_ROW + c * 8 + k1 + 4]; cnt++; }
                    orow[q - 2] = (cnt == 2) ? v * 0.5f : v;
                }
            }
        }
    }
}

extern "C" void kernel_launch(void* const* d_in, const int* in_sizes, int n_in,
                              void* d_out, int out_size)
{
    const float* x  = (const float*)d_in[0];
    const float* W1 = (const float*)d_in[1];
    const float* b1 = (const float*)d_in[2];
    const float* W2 = (const float*)d_in[3];
    const float* b2 = (const float*)d_in[4];
    float* out = (float*)d_out;

    weight_pack_kernel<<<8, 256>>>(W1, W2);

    cudaFuncSetAttribute(fused_hmma_kernel,
                         cudaFuncAttributeMaxDynamicSharedMemorySize, SMEM_BYTES);
    dim3 grid(NBLK, 64);
    fused_hmma_kernel<<<grid, 256, SMEM_BYTES>>>(x, b1, b2, out);
}

// round 15
// speedup vs baseline: 1.2342x; 1.0845x over previous
#include <cuda_runtime.h>
#include <cuda_fp16.h>
#include <math.h>
#include <stdint.h>

// ---------------- problem constants ----------------
#define LEN   16384
#define LOUT  4096
#define PB    127          // primary patches per block
#define PQ    508          // exclusive padded positions per block
#define NBLK  33

// ---------------- smem layout (bytes) ----------------
#define ROWB     144        // fp16 row stride (72 halves): ldmatrix conflict-free
#define OFF_A    0          // A fp16 [128][72]  (feats, then h)
#define OFF_W1   18432      // W1 fp16 [64][72] = 9216B
#define OFF_W2   27648      // W2 fp16 [64][72] = 9216B
#define OFF_HB   36864      // hbuf: [128 rows][144B] (per row: 8ch x float2 k-pairs)
#define OFF_B1S  55296      // float[64]
#define OFF_B2S  55552      // float[64]
#define SMEM_BYTES 55808

// pre-packed fp16 weight image: W1 = words [0,2304), W2 = words [2304,4608)
__device__ uint4 g_wpack4[1152];

__device__ __forceinline__ uint32_t smem_u32(const void* p) {
    uint32_t a;
    asm("{ .reg .u64 t; cvta.to.shared.u64 t, %1; cvt.u32.u64 %0, t; }"
        : "=r"(a) : "l"(p));
    return a;
}

__device__ __forceinline__ void ldsm4(uint32_t r[4], uint32_t addr) {
    asm volatile("ldmatrix.sync.aligned.m8n8.x4.shared.b16 {%0,%1,%2,%3}, [%4];"
                 : "=r"(r[0]), "=r"(r[1]), "=r"(r[2]), "=r"(r[3]) : "r"(addr));
}

__device__ __forceinline__ void mma16816(float c[4], const uint32_t a[4],
                                         const uint32_t* b) {
    asm volatile(
        "mma.sync.aligned.m16n8k16.row.col.f32.f16.f16.f32 "
        "{%0,%1,%2,%3}, {%4,%5,%6,%7}, {%8,%9}, {%0,%1,%2,%3};"
        : "+f"(c[0]), "+f"(c[1]), "+f"(c[2]), "+f"(c[3])
        : "r"(a[0]), "r"(a[1]), "r"(a[2]), "r"(a[3]), "r"(b[0]), "r"(b[1]));
}

__device__ __forceinline__ uint32_t pack_h2(float g0, float g1) {
    uint32_t p;
    asm("cvt.rn.f16x2.f32 %0, %1, %2;" : "=r"(p) : "f"(g1), "f"(g0));
    return p;
}

// fast GELU: tanh form with HW tanh.approx (MUFU). ~6 instructions.
__device__ __forceinline__ float gelu_fast(float v) {
    float u = v * fmaf(0.0356774081f, v * v, 0.7978845608f);
    float t;
    asm("tanh.approx.f32 %0, %1;" : "=f"(t) : "f"(u));
    return fmaf(0.5f * v, t, 0.5f * v);
}

// ---- prep kernel: pack W1/W2 fp32 -> fp16 smem-image in global ----
__global__ void weight_pack_kernel(const float* __restrict__ W1,
                                   const float* __restrict__ W2) {
    uint32_t* w = (uint32_t*)g_wpack4;
    int i = blockIdx.x * 256 + threadIdx.x;      // 0..2047
    if (i >= 2048) return;
    int nr = i >> 5, k2 = (i & 31) << 1;
    int word = nr * 36 + (k2 >> 1);
    w[word]        = pack_h2(W1[nr * 64 + k2], W1[nr * 64 + k2 + 1]);
    w[2304 + word] = pack_h2(W2[nr * 64 + k2], W2[nr * 64 + k2 + 1]);
}

// single-term fp16 GEMM, warp tile 32x32: C[8][4] += A @ W^T
__device__ __forceinline__ void warp_gemm64(uint32_t aB, uint32_t b0, uint32_t b1,
                                            float C[8][4]) {
    #pragma unroll
    for (int ks = 0; ks < 4; ks++) {
        uint32_t a[2][4], b[4][2], r[4];
        ldsm4(a[0], aB + ks * 32);
        ldsm4(a[1], aB + 16 * ROWB + ks * 32);
        ldsm4(r, b0 + ks * 32);
        b[0][0]=r[0]; b[0][1]=r[1]; b[1][0]=r[2]; b[1][1]=r[3];
        ldsm4(r, b1 + ks * 32);
        b[2][0]=r[0]; b[2][1]=r[1]; b[3][0]=r[2]; b[3][1]=r[3];
        #pragma unroll
        for (int i = 0; i < 2; i++)
            #pragma unroll
            for (int j = 0; j < 4; j++)
                mma16816(C[i * 4 + j], a[i], b[j]);
    }
}

__global__ __launch_bounds__(256, 4)
void fused_hmma_kernel(const float* __restrict__ x,
                       const float* __restrict__ b1,
                       const float* __restrict__ b2,
                       float* __restrict__ out)
{
    extern __shared__ char smc[];
    const uint32_t sbase = smem_u32(smc);
    float* b1s = (float*)(smc + OFF_B1S);
    float* b2s = (float*)(smc + OFF_B2S);

    const int tid  = threadIdx.x;
    const int lane = tid & 31;
    const int wid  = tid >> 5;
    const int blk  = blockIdx.x;
    const int n    = blockIdx.y;
    const int wm = wid >> 1, wn = wid & 1;
    const int m0 = 32 * wm,  n0 = 32 * wn;
    const int gid = lane >> 2, tig = lane & 3;

    // lane-resolved ldmatrix offsets
    const uint32_t aOff  = (uint32_t)(m0 + (lane & 15)) * ROWB + (lane >> 4) * 16;
    const uint32_t bOff0 = (uint32_t)(n0 + ((lane >> 4) & 1) * 8 + (lane & 7)) * ROWB
                         + ((lane >> 3) & 1) * 16;
    const uint32_t bOff1 = bOff0 + 16 * ROWB;

    // ---- Phase 1: weights via cp.async; x -> fp16 A (float4 + shfl) ----
    {
        #pragma unroll
        for (int i = 0; i < 5; i++) {
            int idx = tid + 256 * i;
            if (idx < 1152) {
                uint32_t dst = sbase + OFF_W1 + (uint32_t)idx * 16;
                asm volatile("cp.async.cg.shared.global [%0], [%1], 16;"
                             :: "r"(dst), "l"(g_wpack4 + idx));
            }
        }
        asm volatile("cp.async.commit_group;" ::: "memory");

        const float* xn = x + (size_t)n * 8 * LEN;
        const int t = tid & 127;
        const int chalf = tid >> 7;               // 0/1 -> channels 0-3 / 4-7
        const int idx0 = PQ * blk - 6 + 4 * t;    // x index of tap k=0 (≡2 mod 4)
        const bool interior = (idx0 >= 0) && (idx0 + 7 < LEN);
        const bool vok = (idx0 + 2 >= 0) && (idx0 + 5 < LEN);
        #pragma unroll
        for (int cc = 0; cc < 4; cc++) {
            int c = chalf * 4 + cc;
            const float* xp = xn + c * LEN;
            float4 V = make_float4(0.f, 0.f, 0.f, 0.f);
            if (vok) V = *(const float4*)(xp + idx0 + 2);     // taps 2..5, aligned
            float t0 = __shfl_up_sync(0xffffffffu, V.z, 1);
            float t1 = __shfl_up_sync(0xffffffffu, V.w, 1);
            float t6 = __shfl_down_sync(0xffffffffu, V.x, 1);
            float t7 = __shfl_down_sync(0xffffffffu, V.y, 1);
            if (interior) {
                if (lane == 0)  { float2 u = *(const float2*)(xp + idx0);     t0 = u.x; t1 = u.y; }
                if (lane == 31) { float2 u = *(const float2*)(xp + idx0 + 6); t6 = u.x; t7 = u.y; }
                uint4 w;
                w.x = pack_h2(t0, t1);  w.y = pack_h2(V.x, V.y);
                w.z = pack_h2(V.z, V.w); w.w = pack_h2(t6, t7);
                *(uint4*)(smc + OFF_A + t * ROWB + c * 16) = w;
            } else {
                float v[8];
                #pragma unroll
                for (int j = 0; j < 8; j++) {
                    int ix = idx0 + j;
                    v[j] = (ix >= 0 && ix < LEN) ? xp[ix] : 0.0f;
                }
                uint4 w;
                w.x = pack_h2(v[0], v[1]); w.y = pack_h2(v[2], v[3]);
                w.z = pack_h2(v[4], v[5]); w.w = pack_h2(v[6], v[7]);
                *(uint4*)(smc + OFF_A + t * ROWB + c * 16) = w;
            }
        }
        if (tid < 64) { b1s[tid] = b1[tid]; b2s[tid] = b2[tid]; }
        asm volatile("cp.async.wait_group 0;" ::: "memory");
    }
    __syncthreads();

    // ---- GEMM1: feats @ W1^T ----
    float C1[8][4];
    #pragma unroll
    for (int i = 0; i < 8; i++)
        #pragma unroll
        for (int j = 0; j < 4; j++) C1[i][j] = 0.0f;
    warp_gemm64(sbase + OFF_A + aOff,
                sbase + OFF_W1 + bOff0, sbase + OFF_W1 + bOff1, C1);
    // pair barrier: only the 2 warps of this M-band read/write these A rows
    asm volatile("bar.sync %0, 64;" :: "r"(wm + 1) : "memory");

    // ---- Epilogue 1: +b1, fast GELU -> fp16 A region (own band) ----
    #pragma unroll
    for (int i = 0; i < 2; i++) {
        #pragma unroll
        for (int j = 0; j < 4; j++) {
            float* c = C1[i * 4 + j];
            int col = n0 + 8 * j + 2 * tig;
            float bb0 = b1s[col], bb1 = b1s[col + 1];
            int row0 = m0 + 16 * i + gid;
            float g00 = gelu_fast(c[0] + bb0);
            float g01 = gelu_fast(c[1] + bb1);
            float g10 = gelu_fast(c[2] + bb0);
            float g11 = gelu_fast(c[3] + bb1);
            *(uint32_t*)(smc + OFF_A + row0 * ROWB + col * 2) = pack_h2(g00, g01);
            *(uint32_t*)(smc + OFF_A + (row0 + 8) * ROWB + col * 2) = pack_h2(g10, g11);
        }
    }
    asm volatile("bar.sync %0, 64;" :: "r"(wm + 1) : "memory");

    // ---- GEMM2: h @ W2^T ----
    float C2[8][4];
    #pragma unroll
    for (int i = 0; i < 8; i++)
        #pragma unroll
        for (int j = 0; j < 4; j++) C2[i][j] = 0.0f;
    warp_gemm64(sbase + OFF_A + aOff,
                sbase + OFF_W2 + bOff0, sbase + OFF_W2 + bOff1, C2);

    // ---- Epilogue 2': +b2 in regs; tig>=2 store k4..7 halves to hbuf ----
    #pragma unroll
    for (int i = 0; i < 2; i++) {
        #pragma unroll
        for (int j = 0; j < 4; j++) {
            float* c = C2[i * 4 + j];
            int col = n0 + 8 * j + 2 * tig;
            float bb0 = b2s[col], bb1 = b2s[col + 1];
            c[0] += bb0; c[1] += bb1; c[2] += bb0; c[3] += bb1;
            if (tig >= 2) {
                int ch = (n0 >> 3) + j;
                int r0 = m0 + 16 * i + gid;
                *(float2*)(smc + OFF_HB + r0 * 144 + ch * 16 + (tig - 2) * 8) =
                    make_float2(c[0], c[1]);
                *(float2*)(smc + OFF_HB + (r0 + 8) * 144 + ch * 16 + (tig - 2) * 8) =
                    make_float2(c[2], c[3]);
            }
        }
    }
    __syncthreads();

    // ---- Phase 5': register overlap-add; tig<2 write out directly ----
    if (tig < 2) {
        const int lbase = PB * blk - 1;
        float* outn = out + (size_t)n * 8 * LEN;
        if (blk >= 1 && blk <= 31) {
            #pragma unroll
            for (int i = 0; i < 2; i++) {
                #pragma unroll
                for (int j = 0; j < 4; j++) {
                    int ch = (n0 >> 3) + j;
                    float* orow = outn + ch * LEN;
                    float* c = C2[i * 4 + j];
                    #pragma unroll
                    for (int s = 0; s < 2; s++) {
                        int tt = m0 + 16 * i + 8 * s + gid;
                        if (tt == 0) continue;
                        float2 u = *(float2*)(smc + OFF_HB + (tt - 1) * 144
                                              + ch * 16 + tig * 8);
                        float* op = orow + 4 * (lbase + tt) + 2 * tig - 2;
                        *(float2*)op = make_float2(0.5f * (c[2 * s] + u.x),
                                                   0.5f * (c[2 * s + 1] + u.y));
                    }
                }
            }
        } else {
            #pragma unroll
            for (int i = 0; i < 2; i++) {
                #pragma unroll
                for (int j = 0; j < 4; j++) {
                    int ch = (n0 >> 3) + j;
                    float* orow = outn + ch * LEN;
                    float* c = C2[i * 4 + j];
                    #pragma unroll
                    for (int s = 0; s < 2; s++) {
                        int tt = m0 + 16 * i + 8 * s + gid;
                        if (tt == 0) continue;
                        int l1 = lbase + tt;
                        bool has_cur  = (l1 < LOUT);
                        bool has_prev = (l1 >= 1);
                        float v0 = has_cur ? c[2 * s]     : 0.f;
                        float v1 = has_cur ? c[2 * s + 1] : 0.f;
                        float2 u = make_float2(0.f, 0.f);
                        if (has_prev)
                            u = *(float2*)(smc + OFF_HB + (tt - 1) * 144
                                           + ch * 16 + tig * 8);
                        float r0v = v0 + u.x, r1v = v1 + u.y;
                        if (has_cur && has_prev) { r0v *= 0.5f; r1v *= 0.5f; }
                        int q0 = 4 * l1 + 2 * tig;
                        if (q0 >= 2 && q0 <= LEN + 1)     orow[q0 - 2] = r0v;
                        if (q0 + 1 >= 2 && q0 + 1 <= LEN + 1) orow[q0 - 1] = r1v;
                    }
                }
            }
        }
    }
}

extern "C" void kernel_launch(void* const* d_in, const int* in_sizes, int n_in,
                              void* d_out, int out_size)
{
    const float* x  = (const float*)d_in[0];
    const float* W1 = (const float*)d_in[1];
    const float* b1 = (const float*)d_in[2];
    const float* W2 = (const float*)d_in[3];
    const float* b2 = (const float*)d_in[4];
    float* out = (float*)d_out;

    weight_pack_kernel<<<8, 256>>>(W1, W2);

    cudaFuncSetAttribute(fused_hmma_kernel,
                         cudaFuncAttributeMaxDynamicSharedMemorySize, SMEM_BYTES);
    dim3 grid(NBLK, 64);
    fused_hmma_kernel<<<grid, 256, SMEM_BYTES>>>(x, b1, b2, out);
}

// round 16
// speedup vs baseline: 1.2703x; 1.0293x over previous
#include <cuda_runtime.h>
#include <cuda_fp16.h>
#include <math.h>
#include <stdint.h>

// ---------------- problem constants ----------------
#define LEN   16384
#define LOUT  4096
#define PB    127          // primary patches per block
#define PQ    508          // exclusive padded positions per block
#define NBLK  33

// ---------------- smem layout (bytes) ----------------
#define ROWB     144        // fp16 row stride (72 halves): ldmatrix conflict-free
#define OFF_A    0          // A fp16 [128][72]  (feats only; h stays in registers)
#define OFF_W1   18432      // W1 fp16 [64][72] = 9216B
#define OFF_W2   27648      // W2 fp16 [64][72] = 9216B
#define OFF_HB   36864      // hbuf: [128 rows][144B] (per row: 8ch x float2 k4..7)
#define OFF_B1S  55296      // float[64]
#define OFF_B2S  55552      // float[64]
#define SMEM_BYTES 55808

// pre-packed fp16 weight image: W1 = words [0,2304), W2 = words [2304,4608)
__device__ uint4 g_wpack4[1152];

__device__ __forceinline__ uint32_t smem_u32(const void* p) {
    uint32_t a;
    asm("{ .reg .u64 t; cvta.to.shared.u64 t, %1; cvt.u32.u64 %0, t; }"
        : "=r"(a) : "l"(p));
    return a;
}

__device__ __forceinline__ void ldsm4(uint32_t r[4], uint32_t addr) {
    asm volatile("ldmatrix.sync.aligned.m8n8.x4.shared.b16 {%0,%1,%2,%3}, [%4];"
                 : "=r"(r[0]), "=r"(r[1]), "=r"(r[2]), "=r"(r[3]) : "r"(addr));
}

__device__ __forceinline__ void mma16816(float c[4], const uint32_t a[4],
                                         const uint32_t* b) {
    asm volatile(
        "mma.sync.aligned.m16n8k16.row.col.f32.f16.f16.f32 "
        "{%0,%1,%2,%3}, {%4,%5,%6,%7}, {%8,%9}, {%0,%1,%2,%3};"
        : "+f"(c[0]), "+f"(c[1]), "+f"(c[2]), "+f"(c[3])
        : "r"(a[0]), "r"(a[1]), "r"(a[2]), "r"(a[3]), "r"(b[0]), "r"(b[1]));
}

__device__ __forceinline__ uint32_t pack_h2(float g0, float g1) {
    uint32_t p;
    asm("cvt.rn.f16x2.f32 %0, %1, %2;" : "=r"(p) : "f"(g1), "f"(g0));
    return p;
}

// fast GELU: tanh form with HW tanh.approx (MUFU). ~6 instructions.
__device__ __forceinline__ float gelu_fast(float v) {
    float u = v * fmaf(0.0356774081f, v * v, 0.7978845608f);
    float t;
    asm("tanh.approx.f32 %0, %1;" : "=f"(t) : "f"(u));
    return fmaf(0.5f * v, t, 0.5f * v);
}

// ---- prep kernel: pack W1/W2 fp32 -> fp16 smem-image in global ----
__global__ void weight_pack_kernel(const float* __restrict__ W1,
                                   const float* __restrict__ W2) {
    uint32_t* w = (uint32_t*)g_wpack4;
    int i = blockIdx.x * 256 + threadIdx.x;      // 0..2047
    if (i >= 2048) return;
    int nr = i >> 5, k2 = (i & 31) << 1;
    int word = nr * 36 + (k2 >> 1);
    w[word]        = pack_h2(W1[nr * 64 + k2], W1[nr * 64 + k2 + 1]);
    w[2304 + word] = pack_h2(W2[nr * 64 + k2], W2[nr * 64 + k2 + 1]);
}

__global__ __launch_bounds__(256, 4)
void fused_hmma_kernel(const float* __restrict__ x,
                       const float* __restrict__ b1,
                       const float* __restrict__ b2,
                       float* __restrict__ out)
{
    extern __shared__ char smc[];
    const uint32_t sbase = smem_u32(smc);
    float* b1s = (float*)(smc + OFF_B1S);
    float* b2s = (float*)(smc + OFF_B2S);

    const int tid  = threadIdx.x;
    const int lane = tid & 31;
    const int wid  = tid >> 5;          // 0..7, warp owns patch rows wid*16..+15
    const int blk  = blockIdx.x;
    const int n    = blockIdx.y;
    const int m0   = wid * 16;
    const int gid  = lane >> 2, tig = lane & 3;

    // lane-resolved ldmatrix offsets
    const uint32_t aOff = (uint32_t)(m0 + (lane & 15)) * ROWB + (lane >> 4) * 16;
    const uint32_t bOffB = (uint32_t)((lane & 7) + 8 * ((lane >> 4) & 1)) * ROWB
                         + ((lane >> 3) & 1) * 16;

    // ---- Phase 1: weights via cp.async; x -> fp16 A (float4 + shfl) ----
    {
        #pragma unroll
        for (int i = 0; i < 5; i++) {
            int idx = tid + 256 * i;
            if (idx < 1152) {
                uint32_t dst = sbase + OFF_W1 + (uint32_t)idx * 16;
                asm volatile("cp.async.cg.shared.global [%0], [%1], 16;"
                             :: "r"(dst), "l"(g_wpack4 + idx));
            }
        }
        asm volatile("cp.async.commit_group;" ::: "memory");

        const float* xn = x + (size_t)n * 8 * LEN;
        const int t = tid & 127;
        const int chalf = tid >> 7;               // 0/1 -> channels 0-3 / 4-7
        const int idx0 = PQ * blk - 6 + 4 * t;    // x index of tap k=0 (≡2 mod 4)
        const bool interior = (idx0 >= 0) && (idx0 + 7 < LEN);
        const bool vok = (idx0 + 2 >= 0) && (idx0 + 5 < LEN);
        #pragma unroll
        for (int cc = 0; cc < 4; cc++) {
            int c = chalf * 4 + cc;
            const float* xp = xn + c * LEN;
            float4 V = make_float4(0.f, 0.f, 0.f, 0.f);
            if (vok) V = *(const float4*)(xp + idx0 + 2);     // taps 2..5, aligned
            float t0 = __shfl_up_sync(0xffffffffu, V.z, 1);
            float t1 = __shfl_up_sync(0xffffffffu, V.w, 1);
            float t6 = __shfl_down_sync(0xffffffffu, V.x, 1);
            float t7 = __shfl_down_sync(0xffffffffu, V.y, 1);
            if (interior) {
                if (lane == 0)  { float2 u = *(const float2*)(xp + idx0);     t0 = u.x; t1 = u.y; }
                if (lane == 31) { float2 u = *(const float2*)(xp + idx0 + 6); t6 = u.x; t7 = u.y; }
                uint4 w;
                w.x = pack_h2(t0, t1);  w.y = pack_h2(V.x, V.y);
                w.z = pack_h2(V.z, V.w); w.w = pack_h2(t6, t7);
                *(uint4*)(smc + OFF_A + t * ROWB + c * 16) = w;
            } else {
                float v[8];
                #pragma unroll
                for (int j = 0; j < 8; j++) {
                    int ix = idx0 + j;
                    v[j] = (ix >= 0 && ix < LEN) ? xp[ix] : 0.0f;
                }
                uint4 w;
                w.x = pack_h2(v[0], v[1]); w.y = pack_h2(v[2], v[3]);
                w.z = pack_h2(v[4], v[5]); w.w = pack_h2(v[6], v[7]);
                *(uint4*)(smc + OFF_A + t * ROWB + c * 16) = w;
            }
        }
        if (tid < 64) { b1s[tid] = b1[tid]; b2s[tid] = b2[tid]; }
        asm volatile("cp.async.wait_group 0;" ::: "memory");
    }
    __syncthreads();

    // ---- GEMM1: warp stripe M=16 x N=64, K=64. A own rows, full W1. ----
    float C1[8][4];
    #pragma unroll
    for (int j = 0; j < 8; j++)
        #pragma unroll
        for (int q = 0; q < 4; q++) C1[j][q] = 0.0f;
    {
        const uint32_t aB = sbase + OFF_A + aOff;
        const uint32_t bB = sbase + OFF_W1 + bOffB;
        #pragma unroll
        for (int ks = 0; ks < 4; ks++) {
            uint32_t a[4], b[4][2], r[4];
            ldsm4(a, aB + ks * 32);
            #pragma unroll
            for (int half = 0; half < 2; half++) {
                ldsm4(r, bB + (2 * half) * 16 * ROWB + ks * 32);
                b[0][0]=r[0]; b[0][1]=r[1]; b[1][0]=r[2]; b[1][1]=r[3];
                ldsm4(r, bB + (2 * half + 1) * 16 * ROWB + ks * 32);
                b[2][0]=r[0]; b[2][1]=r[1]; b[3][0]=r[2]; b[3][1]=r[3];
                #pragma unroll
                for (int j = 0; j < 4; j++)
                    mma16816(C1[half * 4 + j], a, b[j]);
            }
        }
    }

    // ---- Epilogue 1 (registers): +b1, GELU, pack C1 -> A2 fragments ----
    // A2[ks] = {p01(j=2ks), p23(j=2ks), p01(j=2ks+1), p23(j=2ks+1)}
    uint32_t A2[4][4];
    #pragma unroll
    for (int j = 0; j < 8; j++) {
        int col = 8 * j + 2 * tig;
        float bb0 = b1s[col], bb1 = b1s[col + 1];
        float g0 = gelu_fast(C1[j][0] + bb0);
        float g1 = gelu_fast(C1[j][1] + bb1);
        float g2 = gelu_fast(C1[j][2] + bb0);
        float g3 = gelu_fast(C1[j][3] + bb1);
        A2[j >> 1][(j & 1) * 2 + 0] = pack_h2(g0, g1);
        A2[j >> 1][(j & 1) * 2 + 1] = pack_h2(g2, g3);
    }

    // ---- GEMM2: A2 (registers) @ W2^T, M=16 x N=64, K=64 ----
    float C2[8][4];
    #pragma unroll
    for (int j = 0; j < 8; j++)
        #pragma unroll
        for (int q = 0; q < 4; q++) C2[j][q] = 0.0f;
    {
        const uint32_t bB = sbase + OFF_W2 + bOffB;
        #pragma unroll
        for (int ks = 0; ks < 4; ks++) {
            uint32_t b[4][2], r[4];
            #pragma unroll
            for (int half = 0; half < 2; half++) {
                ldsm4(r, bB + (2 * half) * 16 * ROWB + ks * 32);
                b[0][0]=r[0]; b[0][1]=r[1]; b[1][0]=r[2]; b[1][1]=r[3];
                ldsm4(r, bB + (2 * half + 1) * 16 * ROWB + ks * 32);
                b[2][0]=r[0]; b[2][1]=r[1]; b[3][0]=r[2]; b[3][1]=r[3];
                #pragma unroll
                for (int j = 0; j < 4; j++)
                    mma16816(C2[half * 4 + j], A2[ks], b[j]);
            }
        }
    }

    // ---- Epilogue 2: +b2 in regs; tig>=2 store k4..7 halves to hbuf ----
    #pragma unroll
    for (int j = 0; j < 8; j++) {
        float* c = C2[j];
        int col = 8 * j + 2 * tig;
        float bb0 = b2s[col], bb1 = b2s[col + 1];
        c[0] += bb0; c[1] += bb1; c[2] += bb0; c[3] += bb1;
        if (tig >= 2) {
            int r0 = m0 + gid;
            *(float2*)(smc + OFF_HB + r0 * 144 + j * 16 + (tig - 2) * 8) =
                make_float2(c[0], c[1]);
            *(float2*)(smc + OFF_HB + (r0 + 8) * 144 + j * 16 + (tig - 2) * 8) =
                make_float2(c[2], c[3]);
        }
    }
    __syncthreads();

    // ---- Phase 5: register overlap-add; tig<2 write out directly ----
    if (tig < 2) {
        const int lbase = PB * blk - 1;
        float* outn = out + (size_t)n * 8 * LEN;
        if (blk >= 1 && blk <= 31) {
            #pragma unroll
            for (int j = 0; j < 8; j++) {
                float* orow = outn + j * LEN;
                float* c = C2[j];
                #pragma unroll
                for (int s = 0; s < 2; s++) {
                    int tt = m0 + 8 * s + gid;
                    if (tt == 0) continue;
                    float2 u = *(float2*)(smc + OFF_HB + (tt - 1) * 144
                                          + j * 16 + tig * 8);
                    float* op = orow + 4 * (lbase + tt) + 2 * tig - 2;
                    *(float2*)op = make_float2(0.5f * (c[2 * s] + u.x),
                                               0.5f * (c[2 * s + 1] + u.y));
                }
            }
        } else {
            #pragma unroll
            for (int j = 0; j < 8; j++) {
                float* orow = outn + j * LEN;
                float* c = C2[j];
                #pragma unroll
                for (int s = 0; s < 2; s++) {
                    int tt = m0 + 8 * s + gid;
                    if (tt == 0) continue;
                    int l1 = lbase + tt;
                    bool has_cur  = (l1 < LOUT);
                    bool has_prev = (l1 >= 1);
                    float v0 = has_cur ? c[2 * s]     : 0.f;
                    float v1 = has_cur ? c[2 * s + 1] : 0.f;
                    float2 u = make_float2(0.f, 0.f);
                    if (has_prev)
                        u = *(float2*)(smc + OFF_HB + (tt - 1) * 144
                                       + j * 16 + tig * 8);
                    float r0v = v0 + u.x, r1v = v1 + u.y;
                    if (has_cur && has_prev) { r0v *= 0.5f; r1v *= 0.5f; }
                    int q0 = 4 * l1 + 2 * tig;
                    if (q0 >= 2 && q0 <= LEN + 1)         orow[q0 - 2] = r0v;
                    if (q0 + 1 >= 2 && q0 + 1 <= LEN + 1) orow[q0 - 1] = r1v;
                }
            }
        }
    }
}

extern "C" void kernel_launch(void* const* d_in, const int* in_sizes, int n_in,
                              void* d_out, int out_size)
{
    const float* x  = (const float*)d_in[0];
    const float* W1 = (const float*)d_in[1];
    const float* b1 = (const float*)d_in[2];
    const float* W2 = (const float*)d_in[3];
    const float* b2 = (const float*)d_in[4];
    float* out = (float*)d_out;

    weight_pack_kernel<<<8, 256>>>(W1, W2);

    cudaFuncSetAttribute(fused_hmma_kernel,
                         cudaFuncAttributeMaxDynamicSharedMemorySize, SMEM_BYTES);
    dim3 grid(NBLK, 64);
    fused_hmma_kernel<<<grid, 256, SMEM_BYTES>>>(x, b1, b2, out);
}